// round 15
// baseline (speedup 1.0000x reference)
#include <cuda_runtime.h>
#include <math.h>

typedef unsigned long long u64;

// Problem constants (fixed by the reference)
constexpr int Hc = 512, Wc = 512;
constexpr int Bc = 2, Gc = 4, Fc = 9, Cc = 3;
constexpr int Nn = Hc * Wc;

// Tiling
constexpr int TILE = 32;           // output tile
constexpr int RF   = TILE + 4;     // 36: fM + ew region (2-pixel halo), offset -2
constexpr int RD   = TILE + 2;     // 34: dinv/sig region (1-pixel halo), offset -1
constexpr int NP   = RF * RF;      // 1296: fM plane size
constexpr int NP2  = (RF - 1) * RF;// 1260: ew plane size (row 35 never consumed)
constexpr int ND   = RD * RD;      // 1156

constexpr int NTHREADS = 512;

// SMEM layout (floats). fM pair-planes are dead after phase 2a; sig planes alias them.
constexpr int OFF_EW = 0;
constexpr int SZ_EW  = 5 * NP2;              // 6300 (self,E,SW,S,SE planes, stride NP2)
constexpr int OFF_U  = OFF_EW + SZ_EW;       // 6300 floats (byte 25200, 8B aligned)
constexpr int FA = OFF_U;                    // u64 plane: (v0,v1)  NP entries
constexpr int FB = OFF_U + 2 * NP;           // u64 plane: (v2,v3)
constexpr int FC = OFF_U + 4 * NP;           // u64 plane: (v4,v5)
constexpr int FD = OFF_U + 6 * NP;           // u64 plane: (v6,v7)
constexpr int FE = OFF_U + 8 * NP;           // f32 plane: v8, NP + 40 pad
constexpr int SM_FLOATS = OFF_U + 9 * NP + 40;   // 18004
constexpr int SMEM_BYTES = SM_FLOATS * 4;        // 72016 B -> 3 blocks/SM

// Raw multiM in constant memory (linear layout, single linear D2D copy — no repack
// kernel, no strided 2D memcpy; both cost ~2.5us/replay in the captured graph).
__constant__ float cMf[Gc * Fc * Fc];        // 324 floats

__device__ __forceinline__ u64 pk2(float lo, float hi) {
    u64 r; asm("mov.b64 %0, {%1, %2};" : "=l"(r) : "f"(lo), "f"(hi)); return r;
}
__device__ __forceinline__ void upk2(float& lo, float& hi, u64 v) {
    asm("mov.b64 {%0, %1}, %2;" : "=f"(lo), "=f"(hi) : "l"(v));
}
__device__ __forceinline__ u64 ffma2(u64 a, u64 b, u64 c) {
    u64 d; asm("fma.rn.f32x2 %0, %1, %2, %3;" : "=l"(d) : "l"(a), "l"(b), "l"(c)); return d;
}
__device__ __forceinline__ u64 fmul2(u64 a, u64 b) {
    u64 d; asm("mul.rn.f32x2 %0, %1, %2;" : "=l"(d) : "l"(a), "l"(b)); return d;
}

__device__ __forceinline__ float eclip(float s) {
    // NaN-safe: fmaxf(NaN,-10) = -10
    return __expf(fminf(fmaxf(s, -10.f), 10.f));
}

// Scalar-constant feature transform: loads 9 img floats at p, normalizes, applies M
// via scalar LDC+FFMA (issue-insensitive per R8/R12 evidence; enables linear copy).
// Writes pair-planes at index idx; returns self-similarity dot.
__device__ __forceinline__ float compute_fm(const float* __restrict__ imgbg, int p,
                                            const float* __restrict__ m,
                                            u64* sA, u64* sB, u64* sC, u64* sD,
                                            float* sE, int idx) {
    float acc[9] = {0.f, 0.f, 0.f, 0.f, 0.f, 0.f, 0.f, 0.f, 0.f};
    float ss = 0.f;
    #pragma unroll
    for (int f = 0; f < 9; f++) {
        const float x = __ldg(imgbg + (size_t)f * Nn + p);
        ss = fmaf(x, x, ss);
        #pragma unroll
        for (int v = 0; v < 9; v++) acc[v] = fmaf(x, m[f * 9 + v], acc[v]);
    }
    const float inv = rsqrtf(fmaxf(ss, 1e-24f));
    const float v0 = acc[0] * inv, v1 = acc[1] * inv, v2 = acc[2] * inv;
    const float v3 = acc[3] * inv, v4 = acc[4] * inv, v5 = acc[5] * inv;
    const float v6 = acc[6] * inv, v7 = acc[7] * inv, v8 = acc[8] * inv;
    sA[idx] = pk2(v0, v1);
    sB[idx] = pk2(v2, v3);
    sC[idx] = pk2(v4, v5);
    sD[idx] = pk2(v6, v7);
    sE[idx] = v8;
    float s = v0 * v0;
    s = fmaf(v1, v1, s); s = fmaf(v2, v2, s); s = fmaf(v3, v3, s);
    s = fmaf(v4, v4, s); s = fmaf(v5, v5, s); s = fmaf(v6, v6, s);
    s = fmaf(v7, v7, s); s = fmaf(v8, v8, s);
    return s;
}

// Scalar vector fetch from pair planes (boundary path)
__device__ __forceinline__ void load_vec(const u64* sA, const u64* sB, const u64* sC,
                                         const u64* sD, const float* sE, int idx,
                                         float a[9]) {
    upk2(a[0], a[1], sA[idx]);
    upk2(a[2], a[3], sB[idx]);
    upk2(a[4], a[5], sC[idx]);
    upk2(a[6], a[7], sD[idx]);
    a[8] = sE[idx];
}

__device__ __forceinline__ float dot9s(const float a[9], const float b[9]) {
    float s = a[0] * b[0];
    #pragma unroll
    for (int f = 1; f < 9; f++) s = fmaf(a[f], b[f], s);
    return s;
}

__global__ void __launch_bounds__(NTHREADS, 3)
glr_fused_kernel(const float* __restrict__ img,
                 const float* __restrict__ sig,
                 float* __restrict__ out)
{
    extern __shared__ float sm[];
    float* __restrict__ sEw = sm + OFF_EW;           // 5 planes, stride NP2
    u64*   __restrict__ sA  = reinterpret_cast<u64*>(sm + FA);
    u64*   __restrict__ sB  = reinterpret_cast<u64*>(sm + FB);
    u64*   __restrict__ sC  = reinterpret_cast<u64*>(sm + FC);
    u64*   __restrict__ sD  = reinterpret_cast<u64*>(sm + FD);
    float* __restrict__ sE  = sm + FE;
    // sig planes alias the fM union (fM dead after phase 2a)
    u64*   __restrict__ sP01 = reinterpret_cast<u64*>(sm + OFF_U);  // (s0',s1') ND entries
    float* __restrict__ sP2  = sm + OFF_U + 2 * ND;
    float* __restrict__ sDv  = sm + OFF_U + 3 * ND;

    const int tid = threadIdx.x;
    const int bg  = blockIdx.z;
    const int g   = bg & (Gc - 1);
    const int x0  = blockIdx.x * TILE;
    const int y0  = blockIdx.y * TILE;
    const bool interior = (blockIdx.x >= 1) && (blockIdx.x <= 14) &&
                          (blockIdx.y >= 1) && (blockIdx.y <= 14);

    const float* __restrict__ imgbg = img + (size_t)bg * Fc * Nn;
    const float* __restrict__ sigbg = sig + (size_t)bg * Cc * Nn;
    const float* __restrict__ m = cMf + g * 81;

    // ------- Phase 1: fM pair-planes over 36x36 + self-similarity plane -------
    if (interior) {
        const int pbase = (y0 - 2) * Wc + (x0 - 2);
        for (int idx = tid; idx < NP; idx += NTHREADS) {
            const int ry = idx / RF;
            const int rx = idx - ry * RF;
            const float s = compute_fm(imgbg, pbase + ry * Wc + rx, m,
                                       sA, sB, sC, sD, sE, idx);
            if (idx < NP2) sEw[idx] = eclip(s);   // row 35 self never consumed
        }
    } else {
        for (int idx = tid; idx < NP; idx += NTHREADS) {
            const int ry = idx / RF;
            const int rx = idx - ry * RF;
            const int gy = y0 - 2 + ry;
            const int gx = x0 - 2 + rx;
            if ((unsigned)gy < (unsigned)Hc && (unsigned)gx < (unsigned)Wc) {
                const float s = compute_fm(imgbg, gy * Wc + gx, m,
                                           sA, sB, sC, sD, sE, idx);
                if (idx < NP2) sEw[idx] = eclip(s);
            } else {
                sA[idx] = 0ull; sB[idx] = 0ull; sC[idx] = 0ull; sD[idx] = 0ull;
                sE[idx] = 0.f;
                if (idx < NP2) sEw[idx] = 0.f;
            }
        }
    }
    __syncthreads();

    // ------- Phase 2a: 4-dir ew (E,SW,S,SE) over rows 0..34, paired dots -------
    if (interior) {
        // Unpredicated: region-edge out-of-window reads land in valid smem / pad.
        // Affected ew slots (E col35, SW col0, SE col35) are never consumed.
        for (int idx = tid; idx < NP2; idx += NTHREADS) {
            const u64 a01 = sA[idx], a23 = sB[idx], a45 = sC[idx], a67 = sD[idx];
            const float a8 = sE[idx];
            #pragma unroll
            for (int t = 0; t < 4; t++) {
                const int o = (t == 0) ? 1 : (t == 1) ? (RF - 1) : (t == 2) ? RF : (RF + 1);
                const int j = idx + o;
                u64 acc = fmul2(a01, sA[j]);
                acc = ffma2(a23, sB[j], acc);
                acc = ffma2(a45, sC[j], acc);
                acc = ffma2(a67, sD[j], acc);
                float lo, hi; upk2(lo, hi, acc);
                float s = fmaf(a8, sE[j], lo + hi);
                sEw[(t + 1) * NP2 + idx] = eclip(s);
            }
        }
    } else {
        for (int idx = tid; idx < NP2; idx += NTHREADS) {
            const int ry = idx / RF;
            const int rx = idx - ry * RF;
            const int gy = y0 - 2 + ry;
            const int gx = x0 - 2 + rx;
            if (((unsigned)gy < (unsigned)Hc) && ((unsigned)gx < (unsigned)Wc)) {
                float a[9], b[9];
                load_vec(sA, sB, sC, sD, sE, idx, a);
                float e1 = 0.f, e2 = 0.f, e3 = 0.f, e4 = 0.f;
                if (rx + 1 < RF && (unsigned)(gx + 1) < (unsigned)Wc) {
                    load_vec(sA, sB, sC, sD, sE, idx + 1, b);
                    e1 = eclip(dot9s(a, b));
                }
                if (rx - 1 >= 0 && (unsigned)(gy + 1) < (unsigned)Hc &&
                    (unsigned)(gx - 1) < (unsigned)Wc) {
                    load_vec(sA, sB, sC, sD, sE, idx + RF - 1, b);
                    e2 = eclip(dot9s(a, b));
                }
                if ((unsigned)(gy + 1) < (unsigned)Hc) {
                    load_vec(sA, sB, sC, sD, sE, idx + RF, b);
                    e3 = eclip(dot9s(a, b));
                }
                if (rx + 1 < RF && (unsigned)(gy + 1) < (unsigned)Hc &&
                    (unsigned)(gx + 1) < (unsigned)Wc) {
                    load_vec(sA, sB, sC, sD, sE, idx + RF + 1, b);
                    e4 = eclip(dot9s(a, b));
                }
                sEw[NP2 + idx] = e1; sEw[2 * NP2 + idx] = e2;
                sEw[3 * NP2 + idx] = e3; sEw[4 * NP2 + idx] = e4;
            } else {
                sEw[NP2 + idx] = 0.f; sEw[2 * NP2 + idx] = 0.f;
                sEw[3 * NP2 + idx] = 0.f; sEw[4 * NP2 + idx] = 0.f;
            }
        }
    }
    __syncthreads();

    // ------- Phase 2b: deg -> dinv gather + prescaled paired sig, over 34x34 -------
    if (interior) {
        const int pbase = (y0 - 1) * Wc + (x0 - 1);
        for (int idx = tid; idx < ND; idx += NTHREADS) {
            const int ly = idx / RD;
            const int lx = idx - ly * RD;
            const int r = (ly + 1) * RF + (lx + 1);
            float deg = sEw[r] + sEw[NP2 + r] + sEw[2 * NP2 + r]
                      + sEw[3 * NP2 + r] + sEw[4 * NP2 + r];
            deg += sEw[4 * NP2 + r - RF - 1];  // NW = SE of up-left
            deg += sEw[3 * NP2 + r - RF];      // N  = S  of up
            deg += sEw[2 * NP2 + r - RF + 1];  // NE = SW of up-right
            deg += sEw[NP2 + r - 1];           // W  = E  of left
            const float dinv = rsqrtf(deg);    // deg >= 1
            const int p = pbase + ly * Wc + lx;
            sP01[idx] = pk2(__ldg(sigbg + p) * dinv, __ldg(sigbg + Nn + p) * dinv);
            sP2[idx]  = __ldg(sigbg + 2 * Nn + p) * dinv;
            sDv[idx]  = dinv;
        }
    } else {
        for (int idx = tid; idx < ND; idx += NTHREADS) {
            const int ly = idx / RD;
            const int lx = idx - ly * RD;
            const int gy = y0 - 1 + ly;
            const int gx = x0 - 1 + lx;
            const bool inb = ((unsigned)gy < (unsigned)Hc) && ((unsigned)gx < (unsigned)Wc);
            const int r = (ly + 1) * RF + (lx + 1);
            float dinv = 0.f;
            if (inb) {
                float deg = sEw[r] + sEw[NP2 + r] + sEw[2 * NP2 + r]
                          + sEw[3 * NP2 + r] + sEw[4 * NP2 + r];
                deg += sEw[4 * NP2 + r - RF - 1];
                deg += sEw[3 * NP2 + r - RF];
                deg += sEw[2 * NP2 + r - RF + 1];
                deg += sEw[NP2 + r - 1];
                dinv = rsqrtf(deg);
            }
            const int p = gy * Wc + gx;
            const float s0 = inb ? __ldg(sigbg + p) * dinv          : 0.f;
            const float s1 = inb ? __ldg(sigbg + Nn + p) * dinv     : 0.f;
            const float s2 = inb ? __ldg(sigbg + 2 * Nn + p) * dinv : 0.f;
            sP01[idx] = pk2(s0, s1);
            sP2[idx]  = s2;
            sDv[idx]  = dinv;
        }
    }
    __syncthreads();

    // ---------------- Phase 3: aggregation + output ----------------
    // out_c = s'_c/dp - dp * S_c,  S_c = sum_t ew_t * s'_{c,nb(t)}
    float* __restrict__ outbg = out + (size_t)bg * Cc * Nn;
    for (int idx = tid; idx < TILE * TILE; idx += NTHREADS) {
        const int ly = idx >> 5;
        const int lx = idx & 31;
        const int r = (ly + 2) * RF + (lx + 2);   // region coords
        const int d = (ly + 1) * RD + (lx + 1);   // RD coords

        const float dp = sDv[d];
        u64 S01 = 0ull;
        float S2 = 0.f;

        #define GLR_ACC(nn, ww) do {                     \
            const float _w = (ww);                       \
            const int _n = (nn);                         \
            S01 = ffma2(sP01[_n], pk2(_w, _w), S01);     \
            S2  = fmaf(sP2[_n], _w, S2);                 \
        } while (0)

        GLR_ACC(d - RD - 1, sEw[4 * NP2 + r - RF - 1]);  // NW
        GLR_ACC(d - RD,     sEw[3 * NP2 + r - RF]);      // N
        GLR_ACC(d - RD + 1, sEw[2 * NP2 + r - RF + 1]);  // NE
        GLR_ACC(d - 1,      sEw[NP2 + r - 1]);           // W
        const u64 c01 = sP01[d];
        const float c2 = sP2[d];
        {
            const float w = sEw[r];                      // self
            S01 = ffma2(c01, pk2(w, w), S01);
            S2  = fmaf(c2, w, S2);
        }
        GLR_ACC(d + 1,      sEw[NP2 + r]);               // E
        GLR_ACC(d + RD - 1, sEw[2 * NP2 + r]);           // SW
        GLR_ACC(d + RD,     sEw[3 * NP2 + r]);           // S
        GLR_ACC(d + RD + 1, sEw[4 * NP2 + r]);           // SE
        #undef GLR_ACC

        float S0, S1; upk2(S0, S1, S01);
        float c0, c1; upk2(c0, c1, c01);
        const float inv = __fdividef(1.0f, dp);          // dp in (0,1]
        const int p = (y0 + ly) * Wc + (x0 + lx);
        outbg[p]          = fmaf(-dp, S0, c0 * inv);
        outbg[Nn + p]     = fmaf(-dp, S1, c1 * inv);
        outbg[2 * Nn + p] = fmaf(-dp, S2, c2 * inv);
    }
}

extern "C" void kernel_launch(void* const* d_in, const int* in_sizes, int n_in,
                              void* d_out, int out_size) {
    const float* img = (const float*)d_in[0];  // (B,G,F,H,W)
    const float* sig = (const float*)d_in[1];  // (B,G,C,H,W)
    const float* M   = (const float*)d_in[2];  // (G,F,F)
    float* out = (float*)d_out;

    cudaFuncSetAttribute(glr_fused_kernel,
                         cudaFuncAttributeMaxDynamicSharedMemorySize, SMEM_BYTES);

    // ONE linear D2D copy into constant memory (cheapest prologue variant measured).
    cudaMemcpyToSymbolAsync(cMf, M, Gc * Fc * Fc * sizeof(float), 0,
                            cudaMemcpyDeviceToDevice, 0);

    dim3 grid(Wc / TILE, Hc / TILE, Bc * Gc);
    glr_fused_kernel<<<grid, NTHREADS, SMEM_BYTES>>>(img, sig, out);
}